// round 10
// baseline (speedup 1.0000x reference)
#include <cuda_runtime.h>
#include <cuda_bf16.h>
#include <stdint.h>

#define HID 256
#define OUTC 896
#define N_MAX 100000
#define NPAD_MAX 100096   // 782 * 128
#define NNZ_MAX 3200000
#define SCAN_BLK 1024
#define NBLKS_MAX ((N_MAX + SCAN_BLK - 1) / SCAN_BLK)

// ---------------- device scratch (no allocation allowed) ----------------
__device__ __nv_bfloat16  g_xh[(size_t)NPAD_MAX * HID];     // activation ping, hi
__device__ __nv_bfloat16  g_xlo[(size_t)NPAD_MAX * HID];    // activation ping, lo
__device__ __nv_bfloat16  g_yh[(size_t)NPAD_MAX * HID];     // activation pong, hi
__device__ __nv_bfloat16  g_ylo[(size_t)NPAD_MAX * HID];    // activation pong, lo
__device__ __nv_bfloat16  g_whi[640 * HID];                 // W1(256)|W2(256)|W3(128) hi
__device__ __nv_bfloat16  g_wlo[640 * HID];                 // lo
__device__ int   g_cnt[N_MAX];
__device__ int   g_rowptr[N_MAX + 1];
__device__ int   g_rowfill[N_MAX];
__device__ int2  g_cpack[NNZ_MAX];                          // (col, val bits)
__device__ int   g_blk[NBLKS_MAX];
__device__ int   g_blkoff[NBLKS_MAX];

// ---------------- threefry2x32 (JAX-exact, 20 rounds), partitionable fold ----------------
__device__ __forceinline__ uint32_t tf20_fold(uint32_t k0, uint32_t k1, uint32_t i) {
    uint32_t k2 = k0 ^ k1 ^ 0x1BD11BDAu;
    uint32_t x0 = k0;
    uint32_t x1 = i + k1;
#define R4(a,b,c,d) \
    x0 += x1; x1 = __funnelshift_l(x1, x1, (a)); x1 ^= x0; \
    x0 += x1; x1 = __funnelshift_l(x1, x1, (b)); x1 ^= x0; \
    x0 += x1; x1 = __funnelshift_l(x1, x1, (c)); x1 ^= x0; \
    x0 += x1; x1 = __funnelshift_l(x1, x1, (d)); x1 ^= x0;
    R4(13,15,26,6)
    x0 += k1; x1 += k2 + 1u;
    R4(17,29,16,24)
    x0 += k2; x1 += k0 + 2u;
    R4(13,15,26,6)
    x0 += k0; x1 += k1 + 3u;
    R4(17,29,16,24)
    x0 += k1; x1 += k2 + 4u;
    R4(13,15,26,6)
    x0 += k2; x1 += k0 + 5u;
#undef R4
    return x0 ^ x1;
}

static void h_threefry(uint32_t k0, uint32_t k1, uint32_t x0, uint32_t x1,
                       uint32_t* o0, uint32_t* o1) {
    uint32_t k2 = k0 ^ k1 ^ 0x1BD11BDAu;
#define TFR(r) { x0 += x1; x1 = (x1 << (r)) | (x1 >> (32 - (r))); x1 ^= x0; }
    x0 += k0; x1 += k1;
    TFR(13) TFR(15) TFR(26) TFR(6)
    x0 += k1; x1 += k2 + 1u;
    TFR(17) TFR(29) TFR(16) TFR(24)
    x0 += k2; x1 += k0 + 2u;
    TFR(13) TFR(15) TFR(26) TFR(6)
    x0 += k0; x1 += k1 + 3u;
    TFR(17) TFR(29) TFR(16) TFR(24)
    x0 += k1; x1 += k2 + 4u;
    TFR(13) TFR(15) TFR(26) TFR(6)
    x0 += k2; x1 += k0 + 5u;
#undef TFR
    *o0 = x0; *o1 = x1;
}

__device__ __forceinline__ float drop_apply(float v, uint32_t k0, uint32_t k1, uint32_t idx) {
    uint32_t bits = tf20_fold(k0, k1, idx);
    return ((bits >> 9) < 7549747u) ? v * (1.0f / 0.9f) : 0.0f;
}

// ---------------- CSR build ----------------
__global__ void k_zero_cnt(int n) {
    int i = blockIdx.x * blockDim.x + threadIdx.x;
    if (i < n) g_cnt[i] = 0;
}

__global__ void k_hist(const int* __restrict__ rows, int nnz) {
    int i = blockIdx.x * blockDim.x + threadIdx.x;
    if (i < nnz) atomicAdd(&g_cnt[rows[i]], 1);
}

__global__ void k_scan1(int n) {
    __shared__ int sh[SCAN_BLK];
    int tid = threadIdx.x;
    int i = blockIdx.x * SCAN_BLK + tid;
    int v = (i < n) ? g_cnt[i] : 0;
    sh[tid] = v;
    __syncthreads();
#pragma unroll
    for (int s = 1; s < SCAN_BLK; s <<= 1) {
        int t = (tid >= s) ? sh[tid - s] : 0;
        __syncthreads();
        sh[tid] += t;
        __syncthreads();
    }
    if (i < n) g_rowptr[i] = sh[tid];
    if (tid == SCAN_BLK - 1) g_blk[blockIdx.x] = sh[tid];
}

__global__ void k_scan2(int nblks) {
    __shared__ int sh[128];
    int tid = threadIdx.x;
    int v = (tid < nblks) ? g_blk[tid] : 0;
    sh[tid] = v;
    __syncthreads();
#pragma unroll
    for (int s = 1; s < 128; s <<= 1) {
        int t = (tid >= s) ? sh[tid - s] : 0;
        __syncthreads();
        sh[tid] += t;
        __syncthreads();
    }
    if (tid < nblks) g_blkoff[tid] = sh[tid] - v;
}

__global__ void k_scan3(int n) {
    int i = blockIdx.x * blockDim.x + threadIdx.x;
    if (i >= n) return;
    int incl = g_rowptr[i];
    int excl = g_blkoff[i >> 10] + incl - g_cnt[i];
    g_rowptr[i] = excl;
    g_rowfill[i] = excl;
    if (i == n - 1) g_rowptr[n] = g_blkoff[i >> 10] + incl;
}

__global__ void k_scatter(const int* __restrict__ rows, const int* __restrict__ cols,
                          const float* __restrict__ vals, int nnz) {
    int i = blockIdx.x * blockDim.x + threadIdx.x;
    if (i < nnz) {
        int r = rows[i];
        int p = atomicAdd(&g_rowfill[r], 1);
        g_cpack[p] = make_int2(cols[i], __float_as_int(vals[i]));
    }
}

// ---------------- weight split: W -> bf16 hi/lo ----------------
__global__ void k_wprep(const float* __restrict__ W1, const float* __restrict__ W2,
                        const float* __restrict__ W3) {
    int i = blockIdx.x * blockDim.x + threadIdx.x;
    if (i >= 640 * HID) return;
    float w;
    if (i < 256 * HID)      w = __ldcs(&W1[i]);
    else if (i < 512 * HID) w = __ldcs(&W2[i - 256 * HID]);
    else                    w = __ldcs(&W3[i - 512 * HID]);
    __nv_bfloat16 h = __float2bfloat16(w);
    g_whi[i] = h;
    g_wlo[i] = __float2bfloat16(w - __bfloat162float(h));
}

// ---------------- gather x = embed[x_idx] -> out[:,0:256], xh/xlo ----------------
__global__ void k_gather(const int* __restrict__ idx, const float* __restrict__ emb,
                         float* __restrict__ out, int n) {
    int t = blockIdx.x * blockDim.x + threadIdx.x;
    int total = n * (HID / 4);
    if (t >= total) return;
    int row = t / (HID / 4);
    int c4  = (t % (HID / 4)) * 4;
    int src = __ldg(&idx[row]);
    float4 v = __ldcs((const float4*)(emb + (size_t)src * HID + c4));
    __stcs((float4*)(out + (size_t)row * OUTC + c4), v);
    __nv_bfloat162 h0 = __floats2bfloat162_rn(v.x, v.y);
    __nv_bfloat162 h1 = __floats2bfloat162_rn(v.z, v.w);
    __nv_bfloat162 l0 = __floats2bfloat162_rn(v.x - __bfloat162float(h0.x),
                                              v.y - __bfloat162float(h0.y));
    __nv_bfloat162 l1 = __floats2bfloat162_rn(v.z - __bfloat162float(h1.x),
                                              v.w - __bfloat162float(h1.y));
    uint2 ph, pl;
    ph.x = *(unsigned*)&h0; ph.y = *(unsigned*)&h1;
    pl.x = *(unsigned*)&l0; pl.y = *(unsigned*)&l1;
    *(uint2*)(g_xh  + (size_t)row * HID + c4) = ph;
    *(uint2*)(g_xlo + (size_t)row * HID + c4) = pl;
}

// ---------------- fused layer: spmm(4-row interleaved) + dropout (smem) + bf16x3 HMMA GEMM ----------------
#define LDSM_X4(r, addr) \
    asm volatile("ldmatrix.sync.aligned.m8n8.x4.shared.b16 {%0,%1,%2,%3}, [%4];" \
        : "=r"((r)[0]), "=r"((r)[1]), "=r"((r)[2]), "=r"((r)[3]) : "r"(addr))

#define MMA16816(c, a, b0, b1) \
    asm volatile("mma.sync.aligned.m16n8k16.row.col.f32.bf16.bf16.f32 " \
        "{%0,%1,%2,%3}, {%4,%5,%6,%7}, {%8,%9}, {%0,%1,%2,%3};" \
        : "+f"((c)[0]), "+f"((c)[1]), "+f"((c)[2]), "+f"((c)[3]) \
        : "r"((a)[0]), "r"((a)[1]), "r"((a)[2]), "r"((a)[3]), "r"(b0), "r"(b1))

#define MRS    528                 // m-tile smem row stride (512B data + 16 pad)
#define SM_ML  (128 * MRS)         // 67584: lo tile offset
#define SM_WT  (2 * SM_ML)         // 135168: W chunk offset
// smem total = SM_WT + NOUT*80*2

template<int NOUT>
__global__ __launch_bounds__(512, 1) void k_layer(
    const __nv_bfloat16* __restrict__ xh, const __nv_bfloat16* __restrict__ xlo,
    const __nv_bfloat16* __restrict__ Whi, const __nv_bfloat16* __restrict__ Wlo,
    const float* __restrict__ bias,
    __nv_bfloat16* __restrict__ nextH, __nv_bfloat16* __restrict__ nextL,
    float* __restrict__ outBase, int n, uint32_t k0, uint32_t k1)
{
    extern __shared__ __align__(16) char sm[];
    uint32_t smb;
    asm("{ .reg .u64 t; cvta.to.shared.u64 t, %1; cvt.u32.u64 %0, t; }" : "=r"(smb) : "l"(sm));

    int tid = threadIdx.x;
    int lane = tid & 31, wid = tid >> 5;        // 16 warps
    int brow = blockIdx.x * 128;

    // ================= spmm + residual + dropout phase =================
    // Each warp owns 8 rows, processed as 2 groups of 4 CONCURRENT gather
    // streams -> ~16 loads in flight per warp (MLP recovery vs round 9).
#pragma unroll 1
    for (int g = 0; g < 2; ++g) {
        int lrow0 = wid * 8 + g * 4;
        float acc[4][8];
#pragma unroll
        for (int i = 0; i < 4; ++i)
#pragma unroll
            for (int q = 0; q < 8; ++q) acc[i][q] = 0.f;

        int sidx[4], len[4];
        int maxlen = 0;
#pragma unroll
        for (int i = 0; i < 4; ++i) {
            int grow = brow + lrow0 + i;
            if (grow < n) {
                int s = g_rowptr[grow];
                sidx[i] = s;
                len[i] = g_rowptr[grow + 1] - s;
            } else { sidx[i] = 0; len[i] = 0; }
            maxlen = max(maxlen, len[i]);
        }

#pragma unroll 2
        for (int t = 0; t < maxlen; ++t) {
#pragma unroll
            for (int i = 0; i < 4; ++i) {
                if (t < len[i]) {                 // warp-uniform branch
                    int2  cv = __ldg(&g_cpack[sidx[i] + t]);
                    float v  = __int_as_float(cv.y);
                    uint4 rv = __ldg((const uint4*)(xh + (size_t)cv.x * HID) + lane);
                    acc[i][0] += v * __uint_as_float(rv.x << 16);
                    acc[i][1] += v * __uint_as_float(rv.x & 0xFFFF0000u);
                    acc[i][2] += v * __uint_as_float(rv.y << 16);
                    acc[i][3] += v * __uint_as_float(rv.y & 0xFFFF0000u);
                    acc[i][4] += v * __uint_as_float(rv.z << 16);
                    acc[i][5] += v * __uint_as_float(rv.z & 0xFFFF0000u);
                    acc[i][6] += v * __uint_as_float(rv.w << 16);
                    acc[i][7] += v * __uint_as_float(rv.w & 0xFFFF0000u);
                }
            }
        }

#pragma unroll
        for (int i = 0; i < 4; ++i) {
            int lrow = lrow0 + i;
            int grow = brow + lrow;
            float a0 = acc[i][0], a1 = acc[i][1], a2 = acc[i][2], a3 = acc[i][3];
            float a4 = acc[i][4], a5 = acc[i][5], a6 = acc[i][6], a7 = acc[i][7];
            if (grow < n) {
                uint4 rh = __ldg((const uint4*)(xh  + (size_t)grow * HID) + lane);
                uint4 rl = __ldcs((const uint4*)(xlo + (size_t)grow * HID) + lane);
                a0 += __uint_as_float(rh.x << 16)         + __uint_as_float(rl.x << 16);
                a1 += __uint_as_float(rh.x & 0xFFFF0000u) + __uint_as_float(rl.x & 0xFFFF0000u);
                a2 += __uint_as_float(rh.y << 16)         + __uint_as_float(rl.y << 16);
                a3 += __uint_as_float(rh.y & 0xFFFF0000u) + __uint_as_float(rl.y & 0xFFFF0000u);
                a4 += __uint_as_float(rh.z << 16)         + __uint_as_float(rl.z << 16);
                a5 += __uint_as_float(rh.z & 0xFFFF0000u) + __uint_as_float(rl.z & 0xFFFF0000u);
                a6 += __uint_as_float(rh.w << 16)         + __uint_as_float(rl.w << 16);
                a7 += __uint_as_float(rh.w & 0xFFFF0000u) + __uint_as_float(rl.w & 0xFFFF0000u);

                uint32_t base = (uint32_t)grow * 256u + (uint32_t)lane * 8u;
                a0 = drop_apply(a0, k0, k1, base + 0u);
                a1 = drop_apply(a1, k0, k1, base + 1u);
                a2 = drop_apply(a2, k0, k1, base + 2u);
                a3 = drop_apply(a3, k0, k1, base + 3u);
                a4 = drop_apply(a4, k0, k1, base + 4u);
                a5 = drop_apply(a5, k0, k1, base + 5u);
                a6 = drop_apply(a6, k0, k1, base + 6u);
                a7 = drop_apply(a7, k0, k1, base + 7u);
            }
            __nv_bfloat162 h01 = __floats2bfloat162_rn(a0, a1);
            __nv_bfloat162 h23 = __floats2bfloat162_rn(a2, a3);
            __nv_bfloat162 h45 = __floats2bfloat162_rn(a4, a5);
            __nv_bfloat162 h67 = __floats2bfloat162_rn(a6, a7);
            __nv_bfloat162 l01 = __floats2bfloat162_rn(a0 - __bfloat162float(h01.x),
                                                       a1 - __bfloat162float(h01.y));
            __nv_bfloat162 l23 = __floats2bfloat162_rn(a2 - __bfloat162float(h23.x),
                                                       a3 - __bfloat162float(h23.y));
            __nv_bfloat162 l45 = __floats2bfloat162_rn(a4 - __bfloat162float(h45.x),
                                                       a5 - __bfloat162float(h45.y));
            __nv_bfloat162 l67 = __floats2bfloat162_rn(a6 - __bfloat162float(h67.x),
                                                       a7 - __bfloat162float(h67.y));
            uint4 hh, ll;
            hh.x = *(unsigned*)&h01; hh.y = *(unsigned*)&h23;
            hh.z = *(unsigned*)&h45; hh.w = *(unsigned*)&h67;
            ll.x = *(unsigned*)&l01; ll.y = *(unsigned*)&l23;
            ll.z = *(unsigned*)&l45; ll.w = *(unsigned*)&l67;
            *(uint4*)(sm + lrow * MRS + lane * 16) = hh;
            *(uint4*)(sm + SM_ML + lrow * MRS + lane * 16) = ll;
        }
    }
    __syncthreads();

    // ================= GEMM phase =================
    constexpr int WTN = NOUT / 4;       // warp tile N (64 or 32)
    constexpr int NB = WTN / 8;         // 8 or 4
    constexpr int NPAIR = WTN / 16;     // 4 or 2
    int warpM = wid & 3, warpN = wid >> 2;

    float acc[2 * NB][4];
#pragma unroll
    for (int i = 0; i < 2 * NB; ++i)
#pragma unroll
        for (int q = 0; q < 4; ++q) acc[i][q] = 0.f;

    int lrow16 = lane & 15, lhi = lane >> 4;

#pragma unroll 1
    for (int c = 0; c < 8; ++c) {
        // load W chunk c (NOUT rows x 32 k, hi+lo) into smem
#pragma unroll
        for (int u = tid; u < NOUT * 4; u += 512) {
            int row = u >> 2, q = u & 3;
            uint4 vh = __ldg((const uint4*)(Whi + (size_t)row * HID + c * 32 + q * 8));
            uint4 vl = __ldg((const uint4*)(Wlo + (size_t)row * HID + c * 32 + q * 8));
            *(uint4*)(sm + SM_WT + row * 80 + q * 16) = vh;
            *(uint4*)(sm + SM_WT + NOUT * 80 + row * 80 + q * 16) = vl;
        }
        __syncthreads();

        uint32_t abase = smb + (uint32_t)(warpM * 32 + lrow16) * MRS
                       + (uint32_t)lhi * 16 + (uint32_t)c * 64;
        uint32_t bbase = smb + SM_WT + (uint32_t)(warpN * WTN + lrow16) * 80
                       + (uint32_t)lhi * 16;
#pragma unroll
        for (int kh = 0; kh < 2; ++kh) {
            uint32_t amh[2][4], aml[2][4], bm[NPAIR][4];
            LDSM_X4(amh[0], abase + kh * 32);
            LDSM_X4(amh[1], abase + 16 * MRS + kh * 32);
            LDSM_X4(aml[0], abase + SM_ML + kh * 32);
            LDSM_X4(aml[1], abase + SM_ML + 16 * MRS + kh * 32);
#pragma unroll
            for (int np = 0; np < NPAIR; ++np)
                LDSM_X4(bm[np], bbase + np * 16 * 80 + kh * 32);
            // hh
#pragma unroll
            for (int mb = 0; mb < 2; ++mb)
#pragma unroll
                for (int nb = 0; nb < NB; ++nb)
                    MMA16816(acc[mb * NB + nb], amh[mb],
                             bm[nb >> 1][nb & 1], bm[nb >> 1][(nb & 1) + 2]);
            // lh
#pragma unroll
            for (int mb = 0; mb < 2; ++mb)
#pragma unroll
                for (int nb = 0; nb < NB; ++nb)
                    MMA16816(acc[mb * NB + nb], aml[mb],
                             bm[nb >> 1][nb & 1], bm[nb >> 1][(nb & 1) + 2]);
            // reload bm <- Wlo, hl
#pragma unroll
            for (int np = 0; np < NPAIR; ++np)
                LDSM_X4(bm[np], bbase + NOUT * 80 + np * 16 * 80 + kh * 32);
#pragma unroll
            for (int mb = 0; mb < 2; ++mb)
#pragma unroll
                for (int nb = 0; nb < NB; ++nb)
                    MMA16816(acc[mb * NB + nb], amh[mb],
                             bm[nb >> 1][nb & 1], bm[nb >> 1][(nb & 1) + 2]);
        }
        __syncthreads();
    }

    // ================= epilogue =================
    int rb = brow + warpM * 32 + (lane >> 2);
    int cb = warpN * WTN + (lane & 3) * 2;
#pragma unroll
    for (int mb = 0; mb < 2; ++mb) {
#pragma unroll
        for (int nb = 0; nb < NB; ++nb) {
            float* a = acc[mb * NB + nb];
            int cc = cb + nb * 8;
            float bv0 = __ldg(bias + cc), bv1 = __ldg(bias + cc + 1);
#pragma unroll
            for (int h = 0; h < 2; ++h) {
                int r = rb + mb * 16 + h * 8;
                float v0 = a[h * 2 + 0] + bv0;
                float v1 = a[h * 2 + 1] + bv1;
                v0 = (v0 >= 0.f) ? v0 : 0.2f * v0;
                v1 = (v1 >= 0.f) ? v1 : 0.2f * v1;
                if (nextH) {
                    __nv_bfloat162 hb = __floats2bfloat162_rn(v0, v1);
                    __nv_bfloat162 lb = __floats2bfloat162_rn(v0 - __bfloat162float(hb.x),
                                                              v1 - __bfloat162float(hb.y));
                    *(unsigned*)(nextH + (size_t)r * HID + cc) = *(unsigned*)&hb;
                    __stcs((__nv_bfloat162*)(nextL + (size_t)r * HID + cc), lb);
                }
                if (r < n) __stcs((float2*)(outBase + (size_t)r * OUTC + cc),
                                  make_float2(v0, v1));
            }
        }
    }
}

// ---------------- launch ----------------
extern "C" void kernel_launch(void* const* d_in, const int* in_sizes, int n_in,
                              void* d_out, int out_size) {
    const int*   x_idx = (const int*)d_in[0];
    const float* emb   = (const float*)d_in[1];
    const int*   Grows = (const int*)d_in[2];
    const int*   Gcols = (const int*)d_in[3];
    const float* Gvals = (const float*)d_in[4];
    const float* W1 = (const float*)d_in[5];  const float* b1 = (const float*)d_in[6];
    const float* W2 = (const float*)d_in[7];  const float* b2 = (const float*)d_in[8];
    const float* W3 = (const float*)d_in[9];  const float* b3 = (const float*)d_in[10];
    float* out = (float*)d_out;

    int n   = in_sizes[0];
    int nnz = in_sizes[2];
    if (n > N_MAX) n = N_MAX;
    if (nnz > NNZ_MAX) nnz = NNZ_MAX;
    int npad = ((n + 127) / 128) * 128;
    int nblks = (n + SCAN_BLK - 1) / SCAN_BLK;

    uint32_t keys[3][2];
    for (int j = 0; j < 3; ++j)
        h_threefry(0u, 42u, 0u, (uint32_t)j, &keys[j][0], &keys[j][1]);

    __nv_bfloat16 *xh, *xlo, *yh, *ylo, *whi, *wlo;
    cudaGetSymbolAddress((void**)&xh, g_xh);
    cudaGetSymbolAddress((void**)&xlo, g_xlo);
    cudaGetSymbolAddress((void**)&yh, g_yh);
    cudaGetSymbolAddress((void**)&ylo, g_ylo);
    cudaGetSymbolAddress((void**)&whi, g_whi);
    cudaGetSymbolAddress((void**)&wlo, g_wlo);

    const int SMEM256 = SM_WT + 256 * 80 * 2;   // 176128
    const int SMEM128 = SM_WT + 128 * 80 * 2;   // 155648
    cudaFuncSetAttribute(k_layer<256>, cudaFuncAttributeMaxDynamicSharedMemorySize, SMEM256);
    cudaFuncSetAttribute(k_layer<128>, cudaFuncAttributeMaxDynamicSharedMemorySize, SMEM128);

    // fork: CSR build chain runs concurrently with wprep+gather
    cudaStream_t s2;
    cudaEvent_t eFork, eJoin;
    cudaStreamCreateWithFlags(&s2, cudaStreamNonBlocking);
    cudaEventCreateWithFlags(&eFork, cudaEventDisableTiming);
    cudaEventCreateWithFlags(&eJoin, cudaEventDisableTiming);

    cudaEventRecord(eFork, 0);
    cudaStreamWaitEvent(s2, eFork, 0);

    k_zero_cnt<<<(n + 255) / 256, 256, 0, s2>>>(n);
    k_hist<<<(nnz + 255) / 256, 256, 0, s2>>>(Grows, nnz);
    k_scan1<<<nblks, SCAN_BLK, 0, s2>>>(n);
    k_scan2<<<1, 128, 0, s2>>>(nblks);
    k_scan3<<<(n + 255) / 256, 256, 0, s2>>>(n);
    k_scatter<<<(nnz + 255) / 256, 256, 0, s2>>>(Grows, Gcols, Gvals, nnz);
    cudaEventRecord(eJoin, s2);

    k_wprep<<<640, 256>>>(W1, W2, W3);
    k_gather<<<(n * (HID / 4) + 255) / 256, 256>>>(x_idx, emb, out, n);

    cudaStreamWaitEvent(0, eJoin, 0);

    int grid = npad / 128;

    // layer 1: x (xh/xlo) -> y
    k_layer<256><<<grid, 512, SMEM256>>>(xh, xlo, whi, wlo, b1,
                                         yh, ylo, out + 256, n, keys[0][0], keys[0][1]);
    // layer 2: y -> x
    k_layer<256><<<grid, 512, SMEM256>>>(yh, ylo, whi + 256 * HID, wlo + 256 * HID, b2,
                                         xh, xlo, out + 512, n, keys[1][0], keys[1][1]);
    // layer 3: x -> out only
    k_layer<128><<<grid, 512, SMEM128>>>(xh, xlo, whi + 512 * HID, wlo + 512 * HID, b3,
                                         nullptr, nullptr, out + 768, n, keys[2][0], keys[2][1]);

    cudaEventDestroy(eFork);
    cudaEventDestroy(eJoin);
    cudaStreamDestroy(s2);
}

// round 11
// speedup vs baseline: 2.3757x; 2.3757x over previous
#include <cuda_runtime.h>
#include <cuda_bf16.h>
#include <stdint.h>

#define HID 256
#define OUTC 896
#define N_MAX 100000
#define NPAD_MAX 100096   // 782 * 128
#define NNZ_MAX 3200000
#define SCAN_BLK 1024
#define NBLKS_MAX ((N_MAX + SCAN_BLK - 1) / SCAN_BLK)

// ---------------- device scratch (no allocation allowed) ----------------
__device__ __nv_bfloat16  g_xh[(size_t)NPAD_MAX * HID];     // layer input h, hi part
__device__ __nv_bfloat16  g_xlo[(size_t)NPAD_MAX * HID];    // layer input h, lo part
__device__ __nv_bfloat16  g_mhi[(size_t)NPAD_MAX * HID];    // spmm+dropout out, hi part
__device__ __nv_bfloat16  g_mlo[(size_t)NPAD_MAX * HID];    // lo part
__device__ __nv_bfloat16  g_whi[640 * HID];                 // W1(256)|W2(256)|W3(128) hi
__device__ __nv_bfloat16  g_wlo[640 * HID];                 // lo
__device__ int   g_cnt[N_MAX];
__device__ int   g_rowptr[N_MAX + 1];
__device__ int   g_rowfill[N_MAX];
__device__ int2  g_cpack[NNZ_MAX];                          // (col, val bits)
__device__ int   g_blk[NBLKS_MAX];
__device__ int   g_blkoff[NBLKS_MAX];

// ---------------- threefry2x32 (JAX-exact, 20 rounds), partitionable fold ----------------
__device__ __forceinline__ uint32_t tf20_fold(uint32_t k0, uint32_t k1, uint32_t i) {
    uint32_t k2 = k0 ^ k1 ^ 0x1BD11BDAu;
    uint32_t x0 = k0;
    uint32_t x1 = i + k1;
#define R4(a,b,c,d) \
    x0 += x1; x1 = __funnelshift_l(x1, x1, (a)); x1 ^= x0; \
    x0 += x1; x1 = __funnelshift_l(x1, x1, (b)); x1 ^= x0; \
    x0 += x1; x1 = __funnelshift_l(x1, x1, (c)); x1 ^= x0; \
    x0 += x1; x1 = __funnelshift_l(x1, x1, (d)); x1 ^= x0;
    R4(13,15,26,6)
    x0 += k1; x1 += k2 + 1u;
    R4(17,29,16,24)
    x0 += k2; x1 += k0 + 2u;
    R4(13,15,26,6)
    x0 += k0; x1 += k1 + 3u;
    R4(17,29,16,24)
    x0 += k1; x1 += k2 + 4u;
    R4(13,15,26,6)
    x0 += k2; x1 += k0 + 5u;
#undef R4
    return x0 ^ x1;
}

static void h_threefry(uint32_t k0, uint32_t k1, uint32_t x0, uint32_t x1,
                       uint32_t* o0, uint32_t* o1) {
    uint32_t k2 = k0 ^ k1 ^ 0x1BD11BDAu;
#define TFR(r) { x0 += x1; x1 = (x1 << (r)) | (x1 >> (32 - (r))); x1 ^= x0; }
    x0 += k0; x1 += k1;
    TFR(13) TFR(15) TFR(26) TFR(6)
    x0 += k1; x1 += k2 + 1u;
    TFR(17) TFR(29) TFR(16) TFR(24)
    x0 += k2; x1 += k0 + 2u;
    TFR(13) TFR(15) TFR(26) TFR(6)
    x0 += k0; x1 += k1 + 3u;
    TFR(17) TFR(29) TFR(16) TFR(24)
    x0 += k1; x1 += k2 + 4u;
    TFR(13) TFR(15) TFR(26) TFR(6)
    x0 += k2; x1 += k0 + 5u;
#undef TFR
    *o0 = x0; *o1 = x1;
}

__device__ __forceinline__ float drop_apply(float v, uint32_t k0, uint32_t k1, uint32_t idx) {
    uint32_t bits = tf20_fold(k0, k1, idx);
    return ((bits >> 9) < 7549747u) ? v * (1.0f / 0.9f) : 0.0f;
}

// ---------------- CSR build ----------------
__global__ void k_zero_cnt(int n) {
    int i = blockIdx.x * blockDim.x + threadIdx.x;
    if (i < n) g_cnt[i] = 0;
}

__global__ void k_hist(const int* __restrict__ rows, int nnz) {
    int i = blockIdx.x * blockDim.x + threadIdx.x;
    if (i < nnz) atomicAdd(&g_cnt[rows[i]], 1);
}

__global__ void k_scan1(int n) {
    __shared__ int sh[SCAN_BLK];
    int tid = threadIdx.x;
    int i = blockIdx.x * SCAN_BLK + tid;
    int v = (i < n) ? g_cnt[i] : 0;
    sh[tid] = v;
    __syncthreads();
#pragma unroll
    for (int s = 1; s < SCAN_BLK; s <<= 1) {
        int t = (tid >= s) ? sh[tid - s] : 0;
        __syncthreads();
        sh[tid] += t;
        __syncthreads();
    }
    if (i < n) g_rowptr[i] = sh[tid];
    if (tid == SCAN_BLK - 1) g_blk[blockIdx.x] = sh[tid];
}

__global__ void k_scan2(int nblks) {
    __shared__ int sh[128];
    int tid = threadIdx.x;
    int v = (tid < nblks) ? g_blk[tid] : 0;
    sh[tid] = v;
    __syncthreads();
#pragma unroll
    for (int s = 1; s < 128; s <<= 1) {
        int t = (tid >= s) ? sh[tid - s] : 0;
        __syncthreads();
        sh[tid] += t;
        __syncthreads();
    }
    if (tid < nblks) g_blkoff[tid] = sh[tid] - v;
}

__global__ void k_scan3(int n) {
    int i = blockIdx.x * blockDim.x + threadIdx.x;
    if (i >= n) return;
    int incl = g_rowptr[i];
    int excl = g_blkoff[i >> 10] + incl - g_cnt[i];
    g_rowptr[i] = excl;
    g_rowfill[i] = excl;
    if (i == n - 1) g_rowptr[n] = g_blkoff[i >> 10] + incl;
}

__global__ void k_scatter(const int* __restrict__ rows, const int* __restrict__ cols,
                          const float* __restrict__ vals, int nnz) {
    int i = blockIdx.x * blockDim.x + threadIdx.x;
    if (i < nnz) {
        int r = rows[i];
        int p = atomicAdd(&g_rowfill[r], 1);
        g_cpack[p] = make_int2(cols[i], __float_as_int(vals[i]));
    }
}

// ---------------- weight split: W -> bf16 hi/lo ----------------
__global__ void k_wprep(const float* __restrict__ W1, const float* __restrict__ W2,
                        const float* __restrict__ W3) {
    int i = blockIdx.x * blockDim.x + threadIdx.x;
    if (i >= 640 * HID) return;
    float w;
    if (i < 256 * HID)      w = __ldcs(&W1[i]);
    else if (i < 512 * HID) w = __ldcs(&W2[i - 256 * HID]);
    else                    w = __ldcs(&W3[i - 512 * HID]);
    __nv_bfloat16 h = __float2bfloat16(w);
    g_whi[i] = h;
    g_wlo[i] = __float2bfloat16(w - __bfloat162float(h));
}

// ---------------- gather x = embed[x_idx] -> out[:,0:256], xh/xlo ----------------
__global__ void k_gather(const int* __restrict__ idx, const float* __restrict__ emb,
                         float* __restrict__ out, int n) {
    int t = blockIdx.x * blockDim.x + threadIdx.x;
    int total = n * (HID / 4);
    if (t >= total) return;
    int row = t / (HID / 4);
    int c4  = (t % (HID / 4)) * 4;
    int src = __ldg(&idx[row]);
    float4 v = __ldcs((const float4*)(emb + (size_t)src * HID + c4));
    __stcs((float4*)(out + (size_t)row * OUTC + c4), v);
    __nv_bfloat162 h0 = __floats2bfloat162_rn(v.x, v.y);
    __nv_bfloat162 h1 = __floats2bfloat162_rn(v.z, v.w);
    __nv_bfloat162 l0 = __floats2bfloat162_rn(v.x - __bfloat162float(h0.x),
                                              v.y - __bfloat162float(h0.y));
    __nv_bfloat162 l1 = __floats2bfloat162_rn(v.z - __bfloat162float(h1.x),
                                              v.w - __bfloat162float(h1.y));
    uint2 ph, pl;
    ph.x = *(unsigned*)&h0; ph.y = *(unsigned*)&h1;
    pl.x = *(unsigned*)&l0; pl.y = *(unsigned*)&l1;
    *(uint2*)(g_xh  + (size_t)row * HID + c4) = ph;
    *(uint2*)(g_xlo + (size_t)row * HID + c4) = pl;
}

// ---------------- fused spmm(bf16 gather) + residual(hi+lo) + dropout -> bf16 hi/lo ----------------
__global__ void k_spmm_drop(const __nv_bfloat16* __restrict__ xh,
                            const __nv_bfloat16* __restrict__ xlo,
                            int n, uint32_t k0, uint32_t k1) {
    int row = (blockIdx.x * blockDim.x + threadIdx.x) >> 5;
    if (row >= n) return;
    int lane = threadIdx.x & 31;
    int s = g_rowptr[row], e = g_rowptr[row + 1];
    float a0 = 0.f, a1 = 0.f, a2 = 0.f, a3 = 0.f;
    float a4 = 0.f, a5 = 0.f, a6 = 0.f, a7 = 0.f;
#pragma unroll 2
    for (int p = s; p < e; ++p) {
        int2  cv = __ldg(&g_cpack[p]);
        float v  = __int_as_float(cv.y);
        uint4 rv = __ldg((const uint4*)(xh + (size_t)cv.x * HID) + lane);
        a0 += v * __uint_as_float(rv.x << 16);
        a1 += v * __uint_as_float(rv.x & 0xFFFF0000u);
        a2 += v * __uint_as_float(rv.y << 16);
        a3 += v * __uint_as_float(rv.y & 0xFFFF0000u);
        a4 += v * __uint_as_float(rv.z << 16);
        a5 += v * __uint_as_float(rv.z & 0xFFFF0000u);
        a6 += v * __uint_as_float(rv.w << 16);
        a7 += v * __uint_as_float(rv.w & 0xFFFF0000u);
    }
    // residual = hi + lo
    {
        uint4 rh = __ldg((const uint4*)(xh  + (size_t)row * HID) + lane);
        uint4 rl = __ldcs((const uint4*)(xlo + (size_t)row * HID) + lane);
        a0 += __uint_as_float(rh.x << 16)        + __uint_as_float(rl.x << 16);
        a1 += __uint_as_float(rh.x & 0xFFFF0000u) + __uint_as_float(rl.x & 0xFFFF0000u);
        a2 += __uint_as_float(rh.y << 16)        + __uint_as_float(rl.y << 16);
        a3 += __uint_as_float(rh.y & 0xFFFF0000u) + __uint_as_float(rl.y & 0xFFFF0000u);
        a4 += __uint_as_float(rh.z << 16)        + __uint_as_float(rl.z << 16);
        a5 += __uint_as_float(rh.z & 0xFFFF0000u) + __uint_as_float(rl.z & 0xFFFF0000u);
        a6 += __uint_as_float(rh.w << 16)        + __uint_as_float(rl.w << 16);
        a7 += __uint_as_float(rh.w & 0xFFFF0000u) + __uint_as_float(rl.w & 0xFFFF0000u);
    }

    uint32_t base = (uint32_t)row * 256u + (uint32_t)lane * 8u;
    a0 = drop_apply(a0, k0, k1, base + 0u);
    a1 = drop_apply(a1, k0, k1, base + 1u);
    a2 = drop_apply(a2, k0, k1, base + 2u);
    a3 = drop_apply(a3, k0, k1, base + 3u);
    a4 = drop_apply(a4, k0, k1, base + 4u);
    a5 = drop_apply(a5, k0, k1, base + 5u);
    a6 = drop_apply(a6, k0, k1, base + 6u);
    a7 = drop_apply(a7, k0, k1, base + 7u);

    __nv_bfloat162 h01 = __floats2bfloat162_rn(a0, a1);
    __nv_bfloat162 h23 = __floats2bfloat162_rn(a2, a3);
    __nv_bfloat162 h45 = __floats2bfloat162_rn(a4, a5);
    __nv_bfloat162 h67 = __floats2bfloat162_rn(a6, a7);
    __nv_bfloat162 l01 = __floats2bfloat162_rn(a0 - __bfloat162float(h01.x),
                                               a1 - __bfloat162float(h01.y));
    __nv_bfloat162 l23 = __floats2bfloat162_rn(a2 - __bfloat162float(h23.x),
                                               a3 - __bfloat162float(h23.y));
    __nv_bfloat162 l45 = __floats2bfloat162_rn(a4 - __bfloat162float(h45.x),
                                               a5 - __bfloat162float(h45.y));
    __nv_bfloat162 l67 = __floats2bfloat162_rn(a6 - __bfloat162float(h67.x),
                                               a7 - __bfloat162float(h67.y));
    uint4 hh, ll;
    hh.x = *(unsigned*)&h01; hh.y = *(unsigned*)&h23;
    hh.z = *(unsigned*)&h45; hh.w = *(unsigned*)&h67;
    ll.x = *(unsigned*)&l01; ll.y = *(unsigned*)&l23;
    ll.z = *(unsigned*)&l45; ll.w = *(unsigned*)&l67;
    __stcs((uint4*)(g_mhi + (size_t)row * HID + lane * 8), hh);
    __stcs((uint4*)(g_mlo + (size_t)row * HID + lane * 8), ll);
}

// ---------------- bf16x3 GEMM via warp-level mma.sync (HMMA) ----------------
// 8 K-chunks of 32; per chunk load Ahi/Alo/Whi/Wlo tiles once, 3 MMA passes.
#define LDSM_X4(r, addr) \
    asm volatile("ldmatrix.sync.aligned.m8n8.x4.shared.b16 {%0,%1,%2,%3}, [%4];" \
        : "=r"((r)[0]), "=r"((r)[1]), "=r"((r)[2]), "=r"((r)[3]) : "r"(addr))

#define MMA16816(c, a, b0, b1) \
    asm volatile("mma.sync.aligned.m16n8k16.row.col.f32.bf16.bf16.f32 " \
        "{%0,%1,%2,%3}, {%4,%5,%6,%7}, {%8,%9}, {%0,%1,%2,%3};" \
        : "+f"((c)[0]), "+f"((c)[1]), "+f"((c)[2]), "+f"((c)[3]) \
        : "r"((a)[0]), "r"((a)[1]), "r"((a)[2]), "r"((a)[3]), "r"(b0), "r"(b1))

#define ASTRIDE 80
#define ATILE   (128 * ASTRIDE)     // 10240 bytes
#define STAGE   (4 * ATILE)         // Ahi|Alo|Whi|Wlo = 40960 bytes

__global__ __launch_bounds__(256, 2) void k_gemm_tc(
    const __nv_bfloat16* __restrict__ Ahi, const __nv_bfloat16* __restrict__ Alo,
    const __nv_bfloat16* __restrict__ Whi, const __nv_bfloat16* __restrict__ Wlo,
    const float* __restrict__ bias,
    __nv_bfloat16* __restrict__ nextH, __nv_bfloat16* __restrict__ nextL,
    float* __restrict__ outBase, int n)
{
    extern __shared__ __align__(16) char sm[];   // 2 * STAGE = 81920 B
    uint32_t smb;
    asm("{ .reg .u64 t; cvta.to.shared.u64 t, %1; cvt.u32.u64 %0, t; }" : "=r"(smb) : "l"(sm));

    int tid = threadIdx.x;
    int lane = tid & 31, wid = tid >> 5;
    int warpM = wid & 3, warpN = wid >> 2;
    int brow = blockIdx.x * 128, bcol = blockIdx.y * 128;

    float acc[16][4];
#pragma unroll
    for (int i = 0; i < 16; ++i)
#pragma unroll
        for (int j = 0; j < 4; ++j) acc[i][j] = 0.f;

    int arow = tid >> 1, ahalf = tid & 1;
    int lrow = lane & 15, lhi = lane >> 4;
    uint32_t aoff = (uint32_t)arow * ASTRIDE + (uint32_t)ahalf * 32;

    uint4 rah0, rah1, ral0, ral1, rwh0, rwh1, rwl0, rwl1;
#define LOADG(c) { int kk = (c) * 32; \
    const __nv_bfloat16* aph = Ahi + (size_t)(brow + arow) * HID + kk + ahalf * 16; \
    const __nv_bfloat16* apl = Alo + (size_t)(brow + arow) * HID + kk + ahalf * 16; \
    const __nv_bfloat16* bph = Whi + (size_t)(bcol + arow) * HID + kk + ahalf * 16; \
    const __nv_bfloat16* bpl = Wlo + (size_t)(bcol + arow) * HID + kk + ahalf * 16; \
    rah0 = __ldcs((const uint4*)aph); rah1 = __ldcs((const uint4*)(aph + 8)); \
    ral0 = __ldcs((const uint4*)apl); ral1 = __ldcs((const uint4*)(apl + 8)); \
    rwh0 = __ldg((const uint4*)bph);  rwh1 = __ldg((const uint4*)(bph + 8)); \
    rwl0 = __ldg((const uint4*)bpl);  rwl1 = __ldg((const uint4*)(bpl + 8)); }

#define STORES(st) { char* p = sm + (st) * STAGE + aoff; \
    *(uint4*)p = rah0;                 *(uint4*)(p + 16) = rah1; \
    *(uint4*)(p + ATILE) = ral0;       *(uint4*)(p + ATILE + 16) = ral1; \
    *(uint4*)(p + 2 * ATILE) = rwh0;   *(uint4*)(p + 2 * ATILE + 16) = rwh1; \
    *(uint4*)(p + 3 * ATILE) = rwl0;   *(uint4*)(p + 3 * ATILE + 16) = rwl1; }

    LOADG(0);
    STORES(0);
    __syncthreads();

#pragma unroll 1
    for (int c = 0; c < 8; ++c) {
        if (c + 1 < 8) LOADG(c + 1);
        uint32_t abaseh = smb + (uint32_t)(c & 1) * STAGE
                        + (uint32_t)(warpM * 32 + lrow) * ASTRIDE + (uint32_t)lhi * 16;
        uint32_t bbaseh = smb + (uint32_t)(c & 1) * STAGE + 2 * ATILE
                        + (uint32_t)(warpN * 64 + lrow) * ASTRIDE + (uint32_t)lhi * 16;
#pragma unroll
        for (int kh = 0; kh < 2; ++kh) {
            uint32_t amh[2][4], aml[2][4], bm[4][4];
            LDSM_X4(amh[0], abaseh + kh * 32);
            LDSM_X4(amh[1], abaseh + 16 * ASTRIDE + kh * 32);
            LDSM_X4(aml[0], abaseh + ATILE + kh * 32);
            LDSM_X4(aml[1], abaseh + ATILE + 16 * ASTRIDE + kh * 32);
#pragma unroll
            for (int np = 0; np < 4; ++np)
                LDSM_X4(bm[np], bbaseh + np * 16 * ASTRIDE + kh * 32);
            // pass hh + lh on Whi
#pragma unroll
            for (int mb = 0; mb < 2; ++mb)
#pragma unroll
                for (int nb = 0; nb < 8; ++nb) {
                    MMA16816(acc[mb * 8 + nb], amh[mb],
                             bm[nb >> 1][nb & 1], bm[nb >> 1][(nb & 1) + 2]);
                }
#pragma unroll
            for (int mb = 0; mb < 2; ++mb)
#pragma unroll
                for (int nb = 0; nb < 8; ++nb) {
                    MMA16816(acc[mb * 8 + nb], aml[mb],
                             bm[nb >> 1][nb & 1], bm[nb >> 1][(nb & 1) + 2]);
                }
            // reload bm <- Wlo, pass hl
#pragma unroll
            for (int np = 0; np < 4; ++np)
                LDSM_X4(bm[np], bbaseh + ATILE + np * 16 * ASTRIDE + kh * 32);
#pragma unroll
            for (int mb = 0; mb < 2; ++mb)
#pragma unroll
                for (int nb = 0; nb < 8; ++nb) {
                    MMA16816(acc[mb * 8 + nb], amh[mb],
                             bm[nb >> 1][nb & 1], bm[nb >> 1][(nb & 1) + 2]);
                }
        }
        if (c + 1 < 8) STORES((c + 1) & 1);
        __syncthreads();
    }

    // epilogue: bias + leaky; next-layer hi/lo (resident) + out (stcs)
    int rb = brow + warpM * 32 + (lane >> 2);
    int cb = bcol + warpN * 64 + (lane & 3) * 2;
#pragma unroll
    for (int mb = 0; mb < 2; ++mb) {
#pragma unroll
        for (int nb = 0; nb < 8; ++nb) {
            float* a = acc[mb * 8 + nb];
            int cc = cb + nb * 8;
            float bv0 = __ldg(bias + cc), bv1 = __ldg(bias + cc + 1);
#pragma unroll
            for (int h = 0; h < 2; ++h) {
                int r = rb + mb * 16 + h * 8;
                float v0 = a[h * 2 + 0] + bv0;
                float v1 = a[h * 2 + 1] + bv1;
                v0 = (v0 >= 0.f) ? v0 : 0.2f * v0;
                v1 = (v1 >= 0.f) ? v1 : 0.2f * v1;
                if (nextH) {
                    __nv_bfloat162 hb = __floats2bfloat162_rn(v0, v1);
                    __nv_bfloat162 lb = __floats2bfloat162_rn(v0 - __bfloat162float(hb.x),
                                                              v1 - __bfloat162float(hb.y));
                    *(unsigned*)(nextH + (size_t)r * HID + cc) = *(unsigned*)&hb;
                    __stcs((__nv_bfloat162*)(nextL + (size_t)r * HID + cc), lb);
                }
                if (r < n) __stcs((float2*)(outBase + (size_t)r * OUTC + cc),
                                  make_float2(v0, v1));
            }
        }
    }
}

// ---------------- launch ----------------
extern "C" void kernel_launch(void* const* d_in, const int* in_sizes, int n_in,
                              void* d_out, int out_size) {
    const int*   x_idx = (const int*)d_in[0];
    const float* emb   = (const float*)d_in[1];
    const int*   Grows = (const int*)d_in[2];
    const int*   Gcols = (const int*)d_in[3];
    const float* Gvals = (const float*)d_in[4];
    const float* W1 = (const float*)d_in[5];  const float* b1 = (const float*)d_in[6];
    const float* W2 = (const float*)d_in[7];  const float* b2 = (const float*)d_in[8];
    const float* W3 = (const float*)d_in[9];  const float* b3 = (const float*)d_in[10];
    float* out = (float*)d_out;

    int n   = in_sizes[0];
    int nnz = in_sizes[2];
    if (n > N_MAX) n = N_MAX;
    if (nnz > NNZ_MAX) nnz = NNZ_MAX;
    int npad = ((n + 127) / 128) * 128;
    int nblks = (n + SCAN_BLK - 1) / SCAN_BLK;

    uint32_t keys[3][2];
    for (int j = 0; j < 3; ++j)
        h_threefry(0u, 42u, 0u, (uint32_t)j, &keys[j][0], &keys[j][1]);

    __nv_bfloat16 *xh, *xlo, *mhi, *mlo, *whi, *wlo;
    cudaGetSymbolAddress((void**)&xh, g_xh);
    cudaGetSymbolAddress((void**)&xlo, g_xlo);
    cudaGetSymbolAddress((void**)&mhi, g_mhi);
    cudaGetSymbolAddress((void**)&mlo, g_mlo);
    cudaGetSymbolAddress((void**)&whi, g_whi);
    cudaGetSymbolAddress((void**)&wlo, g_wlo);

    static int smemSet = 0;
    if (!smemSet) {
        cudaFuncSetAttribute(k_gemm_tc, cudaFuncAttributeMaxDynamicSharedMemorySize,
                             2 * STAGE);
        smemSet = 1;
    }

    // fork: CSR build chain runs concurrently with wprep+gather
    cudaStream_t s2;
    cudaEvent_t eFork, eJoin;
    cudaStreamCreateWithFlags(&s2, cudaStreamNonBlocking);
    cudaEventCreateWithFlags(&eFork, cudaEventDisableTiming);
    cudaEventCreateWithFlags(&eJoin, cudaEventDisableTiming);

    cudaEventRecord(eFork, 0);
    cudaStreamWaitEvent(s2, eFork, 0);

    k_zero_cnt<<<(n + 255) / 256, 256, 0, s2>>>(n);
    k_hist<<<(nnz + 255) / 256, 256, 0, s2>>>(Grows, nnz);
    k_scan1<<<nblks, SCAN_BLK, 0, s2>>>(n);
    k_scan2<<<1, 128, 0, s2>>>(nblks);
    k_scan3<<<(n + 255) / 256, 256, 0, s2>>>(n);
    k_scatter<<<(nnz + 255) / 256, 256, 0, s2>>>(Grows, Gcols, Gvals, nnz);
    cudaEventRecord(eJoin, s2);

    k_wprep<<<640, 256>>>(W1, W2, W3);
    k_gather<<<(n * (HID / 4) + 255) / 256, 256>>>(x_idx, emb, out, n);

    cudaStreamWaitEvent(0, eJoin, 0);

    int spmmBlocks = (n + 7) / 8;
    dim3 gemmGrid(npad / 128, 2);
    dim3 gemmGrid3(npad / 128, 1);

    // layer 1
    k_spmm_drop<<<spmmBlocks, 256>>>(xh, xlo, n, keys[0][0], keys[0][1]);
    k_gemm_tc<<<gemmGrid, 256, 2 * STAGE>>>(mhi, mlo, whi, wlo, b1, xh, xlo, out + 256, n);

    // layer 2
    k_spmm_drop<<<spmmBlocks, 256>>>(xh, xlo, n, keys[1][0], keys[1][1]);
    k_gemm_tc<<<gemmGrid, 256, 2 * STAGE>>>(mhi, mlo, whi + 256 * HID, wlo + 256 * HID, b2,
                                            xh, xlo, out + 512, n);

    // layer 3 (output dim 128)
    k_spmm_drop<<<spmmBlocks, 256>>>(xh, xlo, n, keys[2][0], keys[2][1]);
    k_gemm_tc<<<gemmGrid3, 256, 2 * STAGE>>>(mhi, mlo, whi + 512 * HID, wlo + 512 * HID, b3,
                                             nullptr, nullptr, out + 768, n);

    cudaEventDestroy(eFork);
    cudaEventDestroy(eJoin);
    cudaStreamDestroy(s2);
}